// round 1
// baseline (speedup 1.0000x reference)
#include <cuda_runtime.h>
#include <math.h>

#define BATCH 4
#define S 160
#define SS (S*S)
#define VOX (S*S*S)
#define TOT (BATCH*VOX)

#define NB1 6400   // K1: 102400 rows / 16 rows per block
#define NB3 2560   // K2/K3: 4 chunks x 4 batch x 160 planes

// 1D Gaussian taps exp(-t^2/50), t=-4..4
__constant__ float KW[9] = {
  0.72614902f, 0.83527023f, 0.92311633f, 0.98019868f, 1.0f,
  0.98019868f, 0.92311633f, 0.83527023f, 0.72614902f
};
#define KSUM1 7.92946854f

__device__ float  g_t1[TOT];          // after conv-W(labels)
__device__ float  g_t2[TOT];          // after conv-H
__device__ double g_p1[NB1][3];       // per-block partial sums: p, x, x*p
__device__ float  g_mean[2][BATCH];   // class means
__device__ double g_p3[NB3][4];       // per-block partials: n0, d0, n1, d1

__device__ __forceinline__ float edge_sum(int c){
  if (c >= 4 && c < S - 4) return KSUM1;
  float s = 0.f;
  #pragma unroll
  for (int t = -4; t <= 4; t++){
    int p = c + t;
    if (p >= 0 && p < S) s += KW[t + 4];
  }
  return s;
}

__device__ __forceinline__ double blockReduce160(double v, double* sm){
  int t = threadIdx.x;
  sm[t] = v;
  __syncthreads();
  if (t < 32){
    double s = sm[t] + sm[t+32] + sm[t+64] + sm[t+96] + sm[t+128];
    #pragma unroll
    for (int o = 16; o > 0; o >>= 1) s += __shfl_down_sync(0xffffffffu, s, o);
    if (t == 0) sm[0] = s;
  }
  __syncthreads();
  double r = sm[0];
  __syncthreads();
  return r;
}

__device__ __forceinline__ double bred256(double v, double* sm){
  int t = threadIdx.x;
  sm[t] = v; __syncthreads();
  for (int s = 128; s > 0; s >>= 1){
    if (t < s) sm[t] += sm[t + s];
    __syncthreads();
  }
  double r = sm[0];
  __syncthreads();
  return r;
}

// K1: conv along W (contiguous) of labels, fused per-batch sums of p, x, x*p.
__global__ void __launch_bounds__(160) k1_convw_sums(const float* __restrict__ lab,
                                                     const float* __restrict__ inp){
  __shared__ float srow[S];
  __shared__ double sred[S];
  int w = threadIdx.x;
  int row0 = blockIdx.x * 16;   // rows stay within one batch (25600 % 16 == 0)
  float sp = 0.f, si = 0.f, sip = 0.f;
  for (int r = 0; r < 16; r++){
    int base = (row0 + r) * S;
    float l = lab[base + w];
    float x = inp[base + w];
    sp += l; si += x; sip += l * x;
    srow[w] = l;
    __syncthreads();
    float acc = 0.f;
    #pragma unroll
    for (int t = -4; t <= 4; t++){
      int p = w + t;
      if (p >= 0 && p < S) acc = fmaf(KW[t + 4], srow[p], acc);
    }
    g_t1[base + w] = acc;
    __syncthreads();
  }
  double rp  = blockReduce160((double)sp,  sred);
  double ri  = blockReduce160((double)si,  sred);
  double rip = blockReduce160((double)sip, sred);
  if (w == 0){
    g_p1[blockIdx.x][0] = rp;
    g_p1[blockIdx.x][1] = ri;
    g_p1[blockIdx.x][2] = rip;
  }
}

// Kmid: reduce K1 partials -> per-batch class means
__global__ void kmid_means(){
  __shared__ double sm[256];
  int t = threadIdx.x;
  for (int b = 0; b < BATCH; b++){
    double sp = 0, si = 0, sip = 0;
    for (int i = t; i < 1600; i += 256){
      sp  += g_p1[b*1600 + i][0];
      si  += g_p1[b*1600 + i][1];
      sip += g_p1[b*1600 + i][2];
    }
    sp  = bred256(sp,  sm);
    si  = bred256(si,  sm);
    sip = bred256(sip, sm);
    if (t == 0){
      // class_mean = mean(x*cp)/(mean(cp)+1e-5) = S(x*cp)/(S(cp)+1e-5*N)
      double m0 = sip / (sp + 1e-5 * (double)VOX);
      double m1 = (si - sip) / ((double)VOX - sp + 1e-5 * (double)VOX);
      g_mean[0][b] = (float)m0;
      g_mean[1][b] = (float)m1;
    }
    __syncthreads();
  }
}

// K2: conv along H via rolling register window; h-range chunked x4 for occupancy.
__global__ void __launch_bounds__(160) k2_convh(){
  int w = threadIdx.x;
  int bid = blockIdx.x;
  int chunk = bid & 3;
  int bd = bid >> 2;            // (b,d) plane
  int b = bd / S, d = bd - b * S;
  const float* src = g_t1 + b * VOX + d * SS + w;
  float*       dst = g_t2 + b * VOX + d * SS + w;
  int h0 = chunk * 40;
  float win[9];
  #pragma unroll
  for (int i = 0; i < 9; i++){
    int h = h0 - 4 + i;
    win[i] = (h >= 0 && h < S) ? src[h * S] : 0.f;
  }
  #pragma unroll 4
  for (int it = 0; it < 40; it++){
    int oh = h0 + it;
    float acc = 0.f;
    #pragma unroll
    for (int i = 0; i < 9; i++) acc = fmaf(KW[i], win[i], acc);
    dst[oh * S] = acc;
    #pragma unroll
    for (int i = 0; i < 8; i++) win[i] = win[i + 1];
    int nh = oh + 5;
    win[8] = (nh < S) ? src[nh * S] : 0.f;
  }
}

// K3: conv along D (completes G0 = conv3d(p0)) fused with the full weighted
// reduction. G1 = conv3d(1-p0) = closed-form conv3d(ones) - G0.
__global__ void __launch_bounds__(160) k3_convd_reduce(const float* __restrict__ lab,
                                                       const float* __restrict__ inp){
  __shared__ double sred[S];
  int w = threadIdx.x;
  int bid = blockIdx.x;
  int chunk = bid & 3;
  int bh = bid >> 2;            // (b,h) plane
  int b = bh / S, h = bh - b * S;
  int base = b * VOX + h * S + w;
  const float* src = g_t2 + base;
  float m0 = g_mean[0][b], m1 = g_mean[1][b];
  float se_hw = edge_sum(h) * edge_sum(w);
  int d0 = chunk * 40;
  float win[9];
  #pragma unroll
  for (int i = 0; i < 9; i++){
    int d = d0 - 4 + i;
    win[i] = (d >= 0 && d < S) ? src[d * SS] : 0.f;
  }
  float n0 = 0.f, dn0 = 0.f, n1 = 0.f, dn1 = 0.f;
  #pragma unroll 2
  for (int it = 0; it < 40; it++){
    int d = d0 + it;
    float G0 = 0.f;
    #pragma unroll
    for (int i = 0; i < 9; i++) G0 = fmaf(KW[i], win[i], G0);
    float G1 = edge_sum(d) * se_hw - G0;     // conv(1s) - conv(p0)
    int off = base + d * SS;
    float l = lab[off];
    float x = inp[off];
    float q0 = (x - m0) * (x - m0);
    float q1 = (x - m1) * (x - m1);
    float w0 = __expf(-q0 * q0);             // exp(-(diff)^2 / sigma2^2), sigma2=1
    float w1 = __expf(-q1 * q1);
    float t0 = w0 * G0, t1 = w1 * G1;
    n0  = fmaf(l, t0, n0);        dn0 += t0;
    n1  = fmaf(1.f - l, t1, n1);  dn1 += t1;
    #pragma unroll
    for (int i = 0; i < 8; i++) win[i] = win[i + 1];
    int nd = d + 5;
    win[8] = (nd < S) ? src[nd * SS] : 0.f;
  }
  double r0 = blockReduce160((double)n0,  sred);
  double r1 = blockReduce160((double)dn0, sred);
  double r2 = blockReduce160((double)n1,  sred);
  double r3 = blockReduce160((double)dn1, sred);
  if (w == 0){
    g_p3[bid][0] = r0; g_p3[bid][1] = r1;
    g_p3[bid][2] = r2; g_p3[bid][3] = r3;
  }
}

// K4: final scalar
__global__ void k4_finalize(float* __restrict__ out){
  __shared__ double sm[256];
  int t = threadIdx.x;
  double a0 = 0, a1 = 0, a2 = 0, a3 = 0;
  for (int i = t; i < NB3; i += 256){
    a0 += g_p3[i][0]; a1 += g_p3[i][1];
    a2 += g_p3[i][2]; a3 += g_p3[i][3];
  }
  a0 = bred256(a0, sm);
  a1 = bred256(a1, sm);
  a2 = bred256(a2, sm);
  a3 = bred256(a3, sm);
  if (t == 0){
    double loss = fabs(a0 / (a1 + 1e-6)) + fabs(a2 / (a3 + 1e-6));
    out[0] = (float)(2.0 - loss);
  }
}

extern "C" void kernel_launch(void* const* d_in, const int* in_sizes, int n_in,
                              void* d_out, int out_size){
  const float* lab = (const float*)d_in[0];   // labels (metadata order)
  const float* inp = (const float*)d_in[1];   // inputs
  k1_convw_sums<<<NB1, 160>>>(lab, inp);
  k2_convh<<<NB3, 160>>>();
  kmid_means<<<1, 256>>>();
  k3_convd_reduce<<<NB3, 160>>>(lab, inp);
  k4_finalize<<<1, 256>>>((float*)d_out);
}

// round 2
// speedup vs baseline: 1.4530x; 1.4530x over previous
#include <cuda_runtime.h>
#include <cuda_fp16.h>
#include <math.h>

#define BATCH 4
#define S 160
#define SS (S*S)
#define VOX (S*S*S)
#define TOT (BATCH*VOX)

#define NB12 2560  // 4 chunks x (4 batch x 160 d-planes)
#define NB3  2560  // 4 chunks x (4 batch x 160 h-planes)

// 1D Gaussian taps exp(-t^2/50), t=-4..4
__constant__ float KW[9] = {
  0.72614902f, 0.83527023f, 0.92311633f, 0.98019868f, 1.0f,
  0.98019868f, 0.92311633f, 0.83527023f, 0.72614902f
};
#define KSUM1 7.92946854f

__device__ __half  g_t2[TOT];         // conv-W-H of labels (fp16)
__device__ double  g_p1[NB12][3];     // per-block partial sums: p, x, x*p
__device__ float   g_mean[2][BATCH];  // class means
__device__ double  g_p3[NB3][4];      // per-block partials: n0, d0, n1, d1

__device__ __forceinline__ float edge_sum(int c){
  if (c >= 4 && c < S - 4) return KSUM1;
  float s = 0.f;
  #pragma unroll
  for (int t = -4; t <= 4; t++){
    int p = c + t;
    if (p >= 0 && p < S) s += KW[t + 4];
  }
  return s;
}

__device__ __forceinline__ double blockReduce160(double v, double* sm){
  int t = threadIdx.x;
  sm[t] = v;
  __syncthreads();
  if (t < 32){
    double s = sm[t] + sm[t+32] + sm[t+64] + sm[t+96] + sm[t+128];
    #pragma unroll
    for (int o = 16; o > 0; o >>= 1) s += __shfl_down_sync(0xffffffffu, s, o);
    if (t == 0) sm[0] = s;
  }
  __syncthreads();
  double r = sm[0];
  __syncthreads();
  return r;
}

__device__ __forceinline__ double bred256(double v, double* sm){
  int t = threadIdx.x;
  sm[t] = v; __syncthreads();
  for (int s = 128; s > 0; s >>= 1){
    if (t < s) sm[t] += sm[t + s];
    __syncthreads();
  }
  double r = sm[0];
  __syncthreads();
  return r;
}

// K12: fused conv-W + conv-H of labels for one (b, d, h-chunk) tile,
// plus per-batch partial sums of p, x, x*p over the chunk's own rows.
__global__ void __launch_bounds__(160) k12_convwh(const float* __restrict__ lab,
                                                  const float* __restrict__ inp){
  __shared__ float raw[48][168];   // rows h0-4 .. h0+43, cols padded +4 each side
  __shared__ double sred[S];
  int w = threadIdx.x;
  int bid = blockIdx.x;
  int chunk = bid & 3;
  int db = bid >> 2;               // (b,d) plane; b-major so partials group by batch
  int b = db / S, d = db - b * S;
  int h0 = chunk * 40;
  const float* labp = lab + b * VOX + d * SS;
  const float* inpp = inp + b * VOX + d * SS;

  // zero left/right pads
  if (w < 8){
    int c = (w < 4) ? w : (160 + w);   // 0..3 and 164..167
    #pragma unroll 4
    for (int r = 0; r < 48; r++) raw[r][c] = 0.f;
  }

  // load 48 rows (clipped), fused sums over the 40 interior rows
  float sp = 0.f, si = 0.f, sip = 0.f;
  #pragma unroll 4
  for (int r = 0; r < 48; r++){
    int h = h0 - 4 + r;
    float l = (h >= 0 && h < S) ? labp[h * S + w] : 0.f;
    raw[r][4 + w] = l;
    if (r >= 4 && r < 44){
      float x = inpp[(h0 + r - 4) * S + w];
      sp += l; si += x; sip = fmaf(l, x, sip);
    }
  }
  __syncthreads();

  // rolling conv-H window; each new entry is a conv-W of one smem row
  float win[9];
  #pragma unroll
  for (int i = 0; i < 9; i++){
    float a = 0.f;
    #pragma unroll
    for (int t = 0; t < 9; t++) a = fmaf(KW[t], raw[i][w + t], a);
    win[i] = a;
  }
  __half* dst = g_t2 + b * VOX + d * SS + h0 * S + w;
  #pragma unroll 4
  for (int j = 0; j < 40; j++){
    float acc = 0.f;
    #pragma unroll
    for (int i = 0; i < 9; i++) acc = fmaf(KW[i], win[i], acc);
    dst[j * S] = __float2half_rn(acc);
    #pragma unroll
    for (int i = 0; i < 8; i++) win[i] = win[i + 1];
    float a = 0.f;
    #pragma unroll
    for (int t = 0; t < 9; t++) a = fmaf(KW[t], raw[j + 9][w + t], a);
    win[8] = a;
  }

  double rp  = blockReduce160((double)sp,  sred);
  double ri  = blockReduce160((double)si,  sred);
  double rip = blockReduce160((double)sip, sred);
  if (w == 0){
    g_p1[bid][0] = rp;
    g_p1[bid][1] = ri;
    g_p1[bid][2] = rip;
  }
}

// Kmid: reduce K12 partials -> per-batch class means
__global__ void kmid_means(){
  __shared__ double sm[256];
  int t = threadIdx.x;
  for (int b = 0; b < BATCH; b++){
    double sp = 0, si = 0, sip = 0;
    for (int i = t; i < 640; i += 256){
      sp  += g_p1[b*640 + i][0];
      si  += g_p1[b*640 + i][1];
      sip += g_p1[b*640 + i][2];
    }
    sp  = bred256(sp,  sm);
    si  = bred256(si,  sm);
    sip = bred256(sip, sm);
    if (t == 0){
      double m0 = sip / (sp + 1e-5 * (double)VOX);
      double m1 = (si - sip) / ((double)VOX - sp + 1e-5 * (double)VOX);
      g_mean[0][b] = (float)m0;
      g_mean[1][b] = (float)m1;
    }
    __syncthreads();
  }
}

// K3: conv along D (completes G0 = conv3d(p0)) fused with the full weighted
// reduction. G1 = conv3d(1-p0) = closed-form conv3d(ones) - G0.
__global__ void __launch_bounds__(160) k3_convd_reduce(const float* __restrict__ lab,
                                                       const float* __restrict__ inp){
  __shared__ double sred[S];
  int w = threadIdx.x;
  int bid = blockIdx.x;
  int chunk = bid & 3;
  int bh = bid >> 2;            // (b,h) plane
  int b = bh / S, h = bh - b * S;
  int base = b * VOX + h * S + w;
  const __half* src = g_t2 + base;
  float m0 = g_mean[0][b], m1 = g_mean[1][b];
  float se_hw = edge_sum(h) * edge_sum(w);
  int d0 = chunk * 40;
  float win[9];
  #pragma unroll
  for (int i = 0; i < 9; i++){
    int d = d0 - 4 + i;
    win[i] = (d >= 0 && d < S) ? __half2float(src[d * SS]) : 0.f;
  }
  float n0 = 0.f, dn0 = 0.f, n1 = 0.f, dn1 = 0.f;
  #pragma unroll 2
  for (int it = 0; it < 40; it++){
    int d = d0 + it;
    float G0 = 0.f;
    #pragma unroll
    for (int i = 0; i < 9; i++) G0 = fmaf(KW[i], win[i], G0);
    float G1 = edge_sum(d) * se_hw - G0;     // conv(1s) - conv(p0)
    int off = base + d * SS;
    float l = lab[off];
    float x = inp[off];
    float q0 = (x - m0) * (x - m0);
    float q1 = (x - m1) * (x - m1);
    float w0 = __expf(-q0 * q0);             // exp(-(diff)^2 / sigma2^2), sigma2=1
    float w1 = __expf(-q1 * q1);
    float t0 = w0 * G0, t1 = w1 * G1;
    n0  = fmaf(l, t0, n0);        dn0 += t0;
    n1  = fmaf(1.f - l, t1, n1);  dn1 += t1;
    #pragma unroll
    for (int i = 0; i < 8; i++) win[i] = win[i + 1];
    int nd = d + 5;
    win[8] = (nd < S) ? __half2float(src[nd * SS]) : 0.f;
  }
  double r0 = blockReduce160((double)n0,  sred);
  double r1 = blockReduce160((double)dn0, sred);
  double r2 = blockReduce160((double)n1,  sred);
  double r3 = blockReduce160((double)dn1, sred);
  if (w == 0){
    g_p3[bid][0] = r0; g_p3[bid][1] = r1;
    g_p3[bid][2] = r2; g_p3[bid][3] = r3;
  }
}

// K4: final scalar
__global__ void k4_finalize(float* __restrict__ out){
  __shared__ double sm[256];
  int t = threadIdx.x;
  double a0 = 0, a1 = 0, a2 = 0, a3 = 0;
  for (int i = t; i < NB3; i += 256){
    a0 += g_p3[i][0]; a1 += g_p3[i][1];
    a2 += g_p3[i][2]; a3 += g_p3[i][3];
  }
  a0 = bred256(a0, sm);
  a1 = bred256(a1, sm);
  a2 = bred256(a2, sm);
  a3 = bred256(a3, sm);
  if (t == 0){
    double loss = fabs(a0 / (a1 + 1e-6)) + fabs(a2 / (a3 + 1e-6));
    out[0] = (float)(2.0 - loss);
  }
}

extern "C" void kernel_launch(void* const* d_in, const int* in_sizes, int n_in,
                              void* d_out, int out_size){
  const float* lab = (const float*)d_in[0];   // labels
  const float* inp = (const float*)d_in[1];   // inputs
  k12_convwh<<<NB12, 160>>>(lab, inp);
  kmid_means<<<1, 256>>>();
  k3_convd_reduce<<<NB3, 160>>>(lab, inp);
  k4_finalize<<<1, 256>>>((float*)d_out);
}